// round 15
// baseline (speedup 1.0000x reference)
#include <cuda_runtime.h>
#include <cuda_fp16.h>
#include <math.h>

#define BB 8
#define PP 16384
#define QQ 256
#define EE 128
#define NPIX (BB*PP)
#define NPC 9
#define CHUNK 1821              // 9*1821 >= 16384
#define KT 16
#define STG_ 4

// gemm dynamic smem layout (bytes)
#define OFF_8A1 0               // STG_*16*128 = 8192   (fp8 a1 stage)
#define OFF_8A2 8192            // 8192                  (fp8 pp stage)
#define OFF_BS  16384           // STG_*16*272 = 17408   (f16 segval stage)
#define OFF_A1F 33792           // 2*16*272 = 8704       (f16 a1, double buf)
#define OFF_A2F 42496           // 8704                  (f16 pp, double buf)
#define SMEM_TOT 51200

// ---------------- scratch ----------------------------------------------------
__device__ int   g_mask_dtype;
__device__ float g_negsum[BB*QQ];
__device__ float g_psum  [BB*QQ];
__device__ float g_segsum[BB*EE];
__device__ float g_nnz   [BB];
__device__ unsigned char g_a1[NPIX*QQ];   // 33.5 MB (e4m3)
__device__ unsigned char g_pp[NPIX*QQ];   // 33.5 MB (e4m3)
__device__ __half g_bs[NPIX*EE];          // 33.5 MB
__device__ float g_M1[BB*QQ*EE];          // 1 MB
__device__ float g_M2[BB*QQ*EE];          // 1 MB

// ---------------- pre: detect dtype + zero all accumulators ------------------
__global__ void __launch_bounds__(1024) k_pre(const uint4* __restrict__ w, int nvec) {
    const int bid = blockIdx.x, t = threadIdx.x;
    if (bid == 0) {
        __shared__ int sF, sB;
        if (t == 0) { sF = 0; sB = 0; }
        __syncthreads();
        int f = 0, bl = 0;
        for (int i = t; i < nvec; i += 1024) {
            uint4 v = w[i];
            unsigned a[4] = {v.x, v.y, v.z, v.w};
            #pragma unroll
            for (int k = 0; k < 4; k++) {
                if (a[k] == 0x3F800000u) f = 1;
                else if (a[k] & 0xFFFFFF00u) bl = 1;
            }
        }
        if (f)  atomicOr(&sF, 1);
        if (bl) atomicOr(&sB, 1);
        __syncthreads();
        if (t == 0) g_mask_dtype = sF ? 1 : (sB ? 0 : 2);
    } else if (bid <= 32) {
        float4* p = reinterpret_cast<float4*>(g_M1) + (bid - 1) * 2048;
        const float4 z = make_float4(0.f, 0.f, 0.f, 0.f);
        p[t] = z; p[t + 1024] = z;
    } else if (bid <= 64) {
        float4* p = reinterpret_cast<float4*>(g_M2) + (bid - 33) * 2048;
        const float4 z = make_float4(0.f, 0.f, 0.f, 0.f);
        p[t] = z; p[t + 1024] = z;
    } else {
        for (int k = t; k < BB*QQ; k += 1024) { g_negsum[k] = 0.f; g_psum[k] = 0.f; }
        for (int k = t; k < BB*EE; k += 1024) g_segsum[k] = 0.f;
        if (t < BB) g_nnz[t] = 0.f;
    }
}

// ---------------- stage 1: streaming elementwise + softmax -------------------
__global__ void __launch_bounds__(128) k_stage1(
    const float* __restrict__ mlv, const void* __restrict__ maskp,
    const float* __restrict__ seg)
{
    const int b = blockIdx.y, pcb = blockIdx.x;      // 128 chunks of 128 pixels
    const int lane = threadIdx.x & 31, w = threadIdx.x >> 5;
    const int mdt = g_mask_dtype;

    float negacc[8], psacc[8], segacc[4];
    #pragma unroll
    for (int j = 0; j < 8; j++) { negacc[j] = 0.f; psacc[j] = 0.f; }
    #pragma unroll
    for (int j = 0; j < 4; j++) segacc[j] = 0.f;
    float nnzacc = 0.f;

    const size_t base = (size_t)b * PP + pcb * 128;

    for (int pi = w; pi < 128; pi += 4) {
        const size_t pix  = base + pi;
        const size_t rowQ = pix * QQ;

        const float4* xr = reinterpret_cast<const float4*>(mlv + rowQ);
        float4 xa = xr[lane*2], xb = xr[lane*2 + 1];
        float x[8] = {xa.x, xa.y, xa.z, xa.w, xb.x, xb.y, xb.z, xb.w};

        unsigned mbits = 0;
        if (mdt == 0) {
            const unsigned char* mv = (const unsigned char*)maskp + rowQ;
            uint2 u = *reinterpret_cast<const uint2*>(mv + (size_t)lane * 8);
            #pragma unroll
            for (int j = 0; j < 4; j++) {
                if ((u.x >> (8*j)) & 0xffu) mbits |= 1u << j;
                if ((u.y >> (8*j)) & 0xffu) mbits |= 1u << (4 + j);
            }
        } else if (mdt == 1) {
            const float4* mv = reinterpret_cast<const float4*>((const float*)maskp + rowQ);
            float4 a = mv[lane*2], c = mv[lane*2 + 1];
            float mm[8] = {a.x, a.y, a.z, a.w, c.x, c.y, c.z, c.w};
            #pragma unroll
            for (int j = 0; j < 8; j++) if (mm[j] != 0.f) mbits |= 1u << j;
        } else {
            const int4* mv = reinterpret_cast<const int4*>((const int*)maskp + rowQ);
            int4 a = mv[lane*2], c = mv[lane*2 + 1];
            int mm[8] = {a.x, a.y, a.z, a.w, c.x, c.y, c.z, c.w};
            #pragma unroll
            for (int j = 0; j < 8; j++) if (mm[j] != 0) mbits |= 1u << j;
        }

        const float4 sv4 = reinterpret_cast<const float4*>(seg + pix * EE)[lane];
        float sv[4] = {sv4.x, sv4.y, sv4.z, sv4.w};

        // softmax WITHOUT max subtraction (|x| small; values identical)
        float ez[8]; float ssum = 0.f;
        #pragma unroll
        for (int j = 0; j < 8; j++) {
            ez[j] = ((mbits >> j) & 1) ? __expf(x[j]) : 0.f;
            ssum += ez[j];
        }
        #pragma unroll
        for (int o = 16; o; o >>= 1) ssum += __shfl_xor_sync(0xffffffffu, ssum, o);
        const float inv = (ssum > 0.f) ? (1.f / ssum) : 0.f;

        unsigned short a8[4], p8[4];
        #pragma unroll
        for (int j2 = 0; j2 < 4; j2++) {
            float a1v[2] = {0.f, 0.f};
            float pp2[2];
            #pragma unroll
            for (int h = 0; h < 2; h++) {
                const int j = 2*j2 + h;
                pp2[h] = ez[j] * inv;
                if ((mbits >> j) & 1) {
                    a1v[h] = -x[j];
                    // softplus(x) = log(1 + e^x) — reuse the softmax's exp
                    negacc[j] += __logf(1.f + ez[j]);
                    psacc[j]  += pp2[h];
                }
            }
            // pack to e4m3x2 (src1 -> high byte, src2 -> low byte)
            asm("cvt.rn.satfinite.e4m3x2.f32 %0, %1, %2;"
                : "=h"(a8[j2]) : "f"(a1v[1]), "f"(a1v[0]));
            asm("cvt.rn.satfinite.e4m3x2.f32 %0, %1, %2;"
                : "=h"(p8[j2]) : "f"(pp2[1]), "f"(pp2[0]));
        }
        reinterpret_cast<uint2*>(g_a1 + rowQ)[lane] = *reinterpret_cast<uint2*>(a8);
        reinterpret_cast<uint2*>(g_pp + rowQ)[lane] = *reinterpret_cast<uint2*>(p8);

        __half2 bsp[2];
        #pragma unroll
        for (int j2 = 0; j2 < 2; j2++)
            bsp[j2] = __floats2half2_rn(sv[2*j2], sv[2*j2+1]);
        #pragma unroll
        for (int j = 0; j < 4; j++) {
            segacc[j] += sv[j];
            if (sv[j] > 0.f) nnzacc += 1.f;
        }
        reinterpret_cast<uint2*>(g_bs + pix * EE)[lane] = *reinterpret_cast<uint2*>(bsp);
    }

    #pragma unroll
    for (int j = 0; j < 8; j++) {
        if (negacc[j] != 0.f) atomicAdd(&g_negsum[b*QQ + lane*8 + j], negacc[j]);
        if (psacc[j]  != 0.f) atomicAdd(&g_psum  [b*QQ + lane*8 + j], psacc[j]);
    }
    #pragma unroll
    for (int j = 0; j < 4; j++)
        if (segacc[j] != 0.f) atomicAdd(&g_segsum[b*EE + lane*4 + j], segacc[j]);
    #pragma unroll
    for (int o = 16; o; o >>= 1) nnzacc += __shfl_xor_sync(0xffffffffu, nnzacc, o);
    if (lane == 0 && nnzacc != 0.f) atomicAdd(&g_nnz[b], nnzacc);
}

// ---------------- MMA / cp.async helpers -------------------------------------
__device__ __forceinline__ void ldsm4t(unsigned& r0, unsigned& r1, unsigned& r2,
                                       unsigned& r3, const void* p) {
    unsigned a = (unsigned)__cvta_generic_to_shared(p);
    asm volatile("ldmatrix.sync.aligned.m8n8.x4.trans.shared.b16 {%0,%1,%2,%3},[%4];"
                 : "=r"(r0), "=r"(r1), "=r"(r2), "=r"(r3) : "r"(a));
}
__device__ __forceinline__ void mma16816(float* d, const unsigned* a, const unsigned* b) {
    asm volatile("mma.sync.aligned.m16n8k16.row.col.f32.f16.f16.f32 "
                 "{%0,%1,%2,%3},{%4,%5,%6,%7},{%8,%9},{%0,%1,%2,%3};"
                 : "+f"(d[0]), "+f"(d[1]), "+f"(d[2]), "+f"(d[3])
                 : "r"(a[0]), "r"(a[1]), "r"(a[2]), "r"(a[3]), "r"(b[0]), "r"(b[1]));
}
__device__ __forceinline__ void cpa16p(void* dst, const void* src, bool valid) {
    unsigned d = (unsigned)__cvta_generic_to_shared(dst);
    int sz = valid ? 16 : 0;
    asm volatile("cp.async.cg.shared.global [%0], [%1], 16, %2;"
                 :: "r"(d), "l"(src), "r"(sz) : "memory");
}
__device__ __forceinline__ void cpa_commit() {
    asm volatile("cp.async.commit_group;" ::: "memory");
}
template <int N> __device__ __forceinline__ void cpa_wait() {
    asm volatile("cp.async.wait_group %0;" :: "n"(N) : "memory");
}

// ---------------- stage 2: f16 GEMM with fp8 A-operand expansion -------------
__global__ void __launch_bounds__(512) k_gemm() {
    extern __shared__ char sm[];
    const int qh = blockIdx.x, b = blockIdx.y, pc = blockIdx.z;
    const int t = threadIdx.x, lane = t & 31, w = t >> 5;
    const int wq = w & 3, we = w >> 2;                 // 32q x 32e per warp
    const int p0 = pc * CHUNK;
    const int p1c = (p0 + CHUNK < PP) ? p0 + CHUNK : PP;
    const int nkt = (p1c - p0 + KT - 1) / KT;

    float acc1[2][4][4], acc2[2][4][4];
    #pragma unroll
    for (int i = 0; i < 2; i++)
        #pragma unroll
        for (int j = 0; j < 4; j++)
            #pragma unroll
            for (int k = 0; k < 4; k++) { acc1[i][j][k] = 0.f; acc2[i][j][k] = 0.f; }

    // cp.async: t<128: A1 fp8; t<256: A2 fp8; t<512: bs f16
    auto load_tile = [&](int kt, int s) {
        if (t < 256) {
            const int tt = t & 127;
            const int r = tt >> 3, c = tt & 7;
            const int p = p0 + kt * KT + r;
            const bool v = p < p1c;
            const size_t pix = (size_t)b * PP + (v ? p : p0);
            const unsigned char* srcg = (t < 128) ? g_a1 : g_pp;
            const int offb = (t < 128) ? OFF_8A1 : OFF_8A2;
            cpa16p(sm + offb + s * 2048 + r * 128 + c * 16,
                   srcg + pix * QQ + qh * 128 + c * 16, v);
        } else {
            const int tt = t - 256;
            const int r = tt >> 4, c = tt & 15;
            const int p = p0 + kt * KT + r;
            const bool v = p < p1c;
            const size_t pix = (size_t)b * PP + (v ? p : p0);
            cpa16p(sm + OFF_BS + s * 4352 + r * 272 + c * 16,
                   g_bs + pix * EE + c * 8, v);
        }
    };

    // expand fp8 stage s -> f16 buffer buf (each thread: 8 elems)
    auto convert = [&](int s, int buf) {
        const int tt = t & 255;
        const int row = tt >> 4, c8 = tt & 15;
        const char* srcb = sm + ((t < 256) ? OFF_8A1 : OFF_8A2) + s * 2048;
        char*       dstb = sm + ((t < 256) ? OFF_A1F : OFF_A2F) + buf * 4352;
        uint2 v = *reinterpret_cast<const uint2*>(srcb + row * 128 + c8 * 8);
        unsigned short s0 = (unsigned short)(v.x & 0xffff);
        unsigned short s1 = (unsigned short)(v.x >> 16);
        unsigned short s2 = (unsigned short)(v.y & 0xffff);
        unsigned short s3 = (unsigned short)(v.y >> 16);
        unsigned o0, o1, o2, o3;
        asm("cvt.rn.f16x2.e4m3x2 %0, %1;" : "=r"(o0) : "h"(s0));
        asm("cvt.rn.f16x2.e4m3x2 %0, %1;" : "=r"(o1) : "h"(s1));
        asm("cvt.rn.f16x2.e4m3x2 %0, %1;" : "=r"(o2) : "h"(s2));
        asm("cvt.rn.f16x2.e4m3x2 %0, %1;" : "=r"(o3) : "h"(s3));
        *reinterpret_cast<uint4*>(dstb + row * 272 + c8 * 16) = make_uint4(o0, o1, o2, o3);
    };

    // prologue: fill 3 stages, expand tile 0
    #pragma unroll
    for (int s = 0; s < STG_ - 1; s++) {
        if (s < nkt) load_tile(s, s);
        cpa_commit();
    }
    cpa_wait<2>();
    __syncthreads();
    if (nkt > 0) convert(0, 0);

    const int g = lane >> 3, r = lane & 7;
    const __half2 z2 = __floats2half2_rn(0.f, 0.f);

    for (int kt = 0; kt < nkt; kt++) {
        const int buf = kt & 1;
        if (kt + STG_ - 1 < nkt) load_tile(kt + STG_ - 1, (kt + STG_ - 1) & (STG_ - 1));
        cpa_commit();
        cpa_wait<2>();            // stage kt+1 complete
        __syncthreads();          // convert(kt) writes + stage kt+1 visible

        if (kt + 1 < nkt) convert((kt + 1) & (STG_ - 1), buf ^ 1);

        // consume tile kt: A from f16 buf, B from bs stage kt&3
        const int sbf = kt & (STG_ - 1);
        unsigned bs[2][4], bt[2][4];
        const int brow = (g & 1) * 8 + r;
        #pragma unroll
        for (int h = 0; h < 2; h++) {
            const int bcol = we * 32 + h * 16 + (g >> 1) * 8;
            ldsm4t(bs[h][0], bs[h][1], bs[h][2], bs[h][3],
                   sm + OFF_BS + sbf * 4352 + brow * 272 + bcol * 2);
            #pragma unroll
            for (int k = 0; k < 4; k++) {
                __half2 vv = *reinterpret_cast<__half2*>(&bs[h][k]);
                __half2 tv = __hgt2(vv, z2);           // targ = (segval > 0)
                bt[h][k] = *reinterpret_cast<unsigned*>(&tv);
            }
        }
        #pragma unroll
        for (int mt = 0; mt < 2; mt++) {
            const int arow = (g >> 1) * 8 + r;
            const int acol = wq * 32 + mt * 16 + (g & 1) * 8;
            unsigned af1[4], af2[4];
            ldsm4t(af1[0], af1[1], af1[2], af1[3],
                   sm + OFF_A1F + buf * 4352 + arow * 272 + acol * 2);
            ldsm4t(af2[0], af2[1], af2[2], af2[3],
                   sm + OFF_A2F + buf * 4352 + arow * 272 + acol * 2);
            #pragma unroll
            for (int h = 0; h < 2; h++) {
                mma16816(acc1[mt][2*h],     af1, &bt[h][0]);
                mma16816(acc1[mt][2*h + 1], af1, &bt[h][2]);
                mma16816(acc2[mt][2*h],     af2, &bs[h][0]);
                mma16816(acc2[mt][2*h + 1], af2, &bs[h][2]);
            }
        }
        __syncthreads();          // retire readers before buffer/stage reuse
    }

    // flush: global f32 RED (fire-and-forget)
    const size_t pbase = (size_t)b * (QQ * EE);
    #pragma unroll
    for (int mt = 0; mt < 2; mt++) {
        #pragma unroll
        for (int nt = 0; nt < 4; nt++) {
            const int q = qh * 128 + wq * 32 + mt * 16 + (lane >> 2);
            const int e = we * 32 + nt * 8 + (lane & 3) * 2;
            const size_t o1 = pbase + (size_t)q * EE + e;
            const size_t o2 = pbase + (size_t)(q + 8) * EE + e;
            atomicAdd(&g_M1[o1],     acc1[mt][nt][0]);
            atomicAdd(&g_M1[o1 + 1], acc1[mt][nt][1]);
            atomicAdd(&g_M1[o2],     acc1[mt][nt][2]);
            atomicAdd(&g_M1[o2 + 1], acc1[mt][nt][3]);
            atomicAdd(&g_M2[o1],     acc2[mt][nt][0]);
            atomicAdd(&g_M2[o1 + 1], acc2[mt][nt][1]);
            atomicAdd(&g_M2[o2],     acc2[mt][nt][2]);
            atomicAdd(&g_M2[o2 + 1], acc2[mt][nt][3]);
        }
    }
}

// ---------------- final: cheap per-(b,q,e) costs -----------------------------
__global__ void __launch_bounds__(256) k_final(
    const float* __restrict__ logits, const float* __restrict__ ppos,
    const float* __restrict__ chol,   const float* __restrict__ tpos,
    const float* __restrict__ imsz,   float* __restrict__ out)
{
    const int idx = blockIdx.x * 256 + threadIdx.x;
    if (idx >= BB * QQ * EE) return;
    const int e = idx & (EE - 1);
    const int q = (idx >> 7) & (QQ - 1);
    const int b = idx >> 15;

    const float M1 = g_M1[idx];
    const float M2 = g_M2[idx];

    const float lgt = logits[b * QQ + q];
    const float cls = fmaxf(-lgt, 0.f) + log1pf(__expf(-fabsf(lgt)));
    const float nnz = fmaxf(g_nnz[b], 1.f);
    const float maskc = (M1 + g_negsum[b * QQ + q]) / nnz;
    const float dice  = 1.f - (2.f * M2 + 1.f) / (g_psum[b * QQ + q] + g_segsum[b * EE + e] + 1.f);

    const float px = ppos[(b * QQ + q) * 2 + 0], py = ppos[(b * QQ + q) * 2 + 1];
    const float tx = tpos[(b * EE + e) * 2 + 0], ty = tpos[(b * EE + e) * 2 + 1];
    const float d0 = px - tx, d1 = py - ty;
    const float a0 = fabsf(d0), a1 = fabsf(d1);
    const float h0 = (a0 < 1.f) ? 0.5f * d0 * d0 : a0 - 0.5f;
    const float h1 = (a1 < 1.f) ? 0.5f * d1 * d1 : a1 - 0.5f;
    const float hub = 0.5f * (h0 + h1);

    const float sx = imsz[b * 2 + 0], sy = imsz[b * 2 + 1];
    const float L00 = chol[(b * QQ + q) * 4 + 0];
    const float L10 = chol[(b * QQ + q) * 4 + 2];
    const float L11 = chol[(b * QQ + q) * 4 + 3];
    const float D0 = (tx - px) * sx, D1 = (ty - py) * sy;
    const float z0 = D0 / L00;
    const float z1 = (D1 - L10 * z0) / L11;
    const float nll = 0.5f * (z0 * z0 + z1 * z1) + 1.837877066409345f + logf(L00) + logf(L11);
    const float lik = 1.f - __expf(-nll);

    out[idx] = 2.f * cls + 5.f * maskc + 5.f * dice + hub + 0.5f * nll + 0.5f * lik;
}

// ---------------- launch -----------------------------------------------------
extern "C" void kernel_launch(void* const* d_in, const int* in_sizes, int n_in,
                              void* d_out, int out_size)
{
    const float* pred_logits = (const float*)d_in[0];
    const float* mlv         = (const float*)d_in[1];
    const void*  mm          = d_in[2];
    const float* seg         = (const float*)d_in[3];
    const float* ppos        = (const float*)d_in[4];
    const float* chol        = (const float*)d_in[5];
    const float* tpos        = (const float*)d_in[6];
    const float* imsz        = (const float*)d_in[7];
    float* out = (float*)d_out;

    int nvec = in_sizes[2] / 16;
    if (nvec > 4096) nvec = 4096;

    k_pre<<<66, 1024>>>((const uint4*)mm, nvec);

    dim3 g1(128, BB);
    k_stage1<<<g1, 128>>>(mlv, mm, seg);

    cudaFuncSetAttribute(k_gemm, cudaFuncAttributeMaxDynamicSharedMemorySize, SMEM_TOT);
    dim3 g2(2, BB, NPC);
    k_gemm<<<g2, 512, SMEM_TOT>>>();

    k_final<<<(BB * QQ * EE + 255) / 256, 256>>>(pred_logits, ppos, chol, tpos, imsz, out);
}

// round 16
// speedup vs baseline: 1.1008x; 1.1008x over previous
#include <cuda_runtime.h>
#include <cuda_fp16.h>
#include <math.h>

#define BB 8
#define PP 16384
#define QQ 256
#define EE 128
#define NPIX (BB*PP)
#define NPC 9
#define CHUNK 1821              // 9*1821 >= 16384
#define KT 16
#define SA 136
#define SB 136
#define STG_ 4

// ---------------- scratch ----------------------------------------------------
__device__ int   g_mask_dtype;
__device__ float g_negsum[BB*QQ];
__device__ float g_psum  [BB*QQ];
__device__ float g_segsum[BB*EE];
__device__ float g_nnz   [BB];
__device__ __half g_a1[NPIX*QQ];          // 67 MB
__device__ __half g_pp[NPIX*QQ];          // 67 MB
__device__ __half g_bs[NPIX*EE];          // 33.5 MB
__device__ float g_M1[BB*QQ*EE];          // 1 MB (self-zeroed by k_final)
__device__ float g_M2[BB*QQ*EE];          // 1 MB (self-zeroed by k_final)

// ---------------- pre: detect dtype (block 0) + zero stats (block 1) ---------
__global__ void __launch_bounds__(1024) k_pre(const uint4* __restrict__ w, int nvec) {
    const int t = threadIdx.x;
    if (blockIdx.x == 0) {
        __shared__ int sF, sB;
        if (t == 0) { sF = 0; sB = 0; }
        __syncthreads();
        int f = 0, bl = 0;
        for (int i = t; i < nvec; i += 1024) {
            uint4 v = w[i];
            unsigned a[4] = {v.x, v.y, v.z, v.w};
            #pragma unroll
            for (int k = 0; k < 4; k++) {
                if (a[k] == 0x3F800000u) f = 1;
                else if (a[k] & 0xFFFFFF00u) bl = 1;
            }
        }
        if (f)  atomicOr(&sF, 1);
        if (bl) atomicOr(&sB, 1);
        __syncthreads();
        if (t == 0) g_mask_dtype = sF ? 1 : (sB ? 0 : 2);
    } else {
        for (int k = t; k < BB*QQ; k += 1024) { g_negsum[k] = 0.f; g_psum[k] = 0.f; }
        for (int k = t; k < BB*EE; k += 1024) g_segsum[k] = 0.f;
        if (t < BB) g_nnz[t] = 0.f;
    }
}

// ---------------- stage 1: streaming elementwise + softmax -------------------
__global__ void __launch_bounds__(128) k_stage1(
    const float* __restrict__ mlv, const void* __restrict__ maskp,
    const float* __restrict__ seg)
{
    const int b = blockIdx.y, pcb = blockIdx.x;      // 128 chunks of 128 pixels
    const int lane = threadIdx.x & 31, w = threadIdx.x >> 5;
    const int mdt = g_mask_dtype;

    float negacc[8], psacc[8], segacc[4];
    #pragma unroll
    for (int j = 0; j < 8; j++) { negacc[j] = 0.f; psacc[j] = 0.f; }
    #pragma unroll
    for (int j = 0; j < 4; j++) segacc[j] = 0.f;
    float nnzacc = 0.f;

    const size_t base = (size_t)b * PP + pcb * 128;

    for (int pi = w; pi < 128; pi += 4) {
        const size_t pix  = base + pi;
        const size_t rowQ = pix * QQ;

        const float4* xr = reinterpret_cast<const float4*>(mlv + rowQ);
        float4 xa = __ldcs(xr + lane*2), xb = __ldcs(xr + lane*2 + 1);
        float x[8] = {xa.x, xa.y, xa.z, xa.w, xb.x, xb.y, xb.z, xb.w};

        unsigned mbits = 0;
        if (mdt == 0) {
            const unsigned char* mv = (const unsigned char*)maskp + rowQ;
            uint2 u = __ldcs(reinterpret_cast<const uint2*>(mv + (size_t)lane * 8));
            #pragma unroll
            for (int j = 0; j < 4; j++) {
                if ((u.x >> (8*j)) & 0xffu) mbits |= 1u << j;
                if ((u.y >> (8*j)) & 0xffu) mbits |= 1u << (4 + j);
            }
        } else if (mdt == 1) {
            const float4* mv = reinterpret_cast<const float4*>((const float*)maskp + rowQ);
            float4 a = __ldcs(mv + lane*2), c = __ldcs(mv + lane*2 + 1);
            float mm[8] = {a.x, a.y, a.z, a.w, c.x, c.y, c.z, c.w};
            #pragma unroll
            for (int j = 0; j < 8; j++) if (mm[j] != 0.f) mbits |= 1u << j;
        } else {
            const int4* mv = reinterpret_cast<const int4*>((const int*)maskp + rowQ);
            int4 a = __ldcs(mv + lane*2), c = __ldcs(mv + lane*2 + 1);
            int mm[8] = {a.x, a.y, a.z, a.w, c.x, c.y, c.z, c.w};
            #pragma unroll
            for (int j = 0; j < 8; j++) if (mm[j] != 0) mbits |= 1u << j;
        }

        const float4 sv4 = __ldcs(reinterpret_cast<const float4*>(seg + pix * EE) + lane);
        float sv[4] = {sv4.x, sv4.y, sv4.z, sv4.w};

        // softmax WITHOUT max subtraction (|x| small; values identical)
        float ez[8]; float ssum = 0.f;
        #pragma unroll
        for (int j = 0; j < 8; j++) {
            ez[j] = ((mbits >> j) & 1) ? __expf(x[j]) : 0.f;
            ssum += ez[j];
        }
        #pragma unroll
        for (int o = 16; o; o >>= 1) ssum += __shfl_xor_sync(0xffffffffu, ssum, o);
        const float inv = (ssum > 0.f) ? (1.f / ssum) : 0.f;

        __half2 a1p[4], ppp[4];
        #pragma unroll
        for (int j2 = 0; j2 < 4; j2++) {
            float a1v[2] = {0.f, 0.f};
            float pp2[2];
            #pragma unroll
            for (int h = 0; h < 2; h++) {
                const int j = 2*j2 + h;
                pp2[h] = ez[j] * inv;
                if ((mbits >> j) & 1) {
                    a1v[h] = -x[j];
                    // softplus(x) = log(1 + e^x) — reuse the softmax's exp
                    negacc[j] += __logf(1.f + ez[j]);
                    psacc[j]  += pp2[h];
                }
            }
            a1p[j2] = __floats2half2_rn(a1v[0], a1v[1]);
            ppp[j2] = __floats2half2_rn(pp2[0], pp2[1]);
        }
        __stwt(reinterpret_cast<uint4*>(g_a1 + rowQ) + lane, *reinterpret_cast<uint4*>(a1p));
        __stwt(reinterpret_cast<uint4*>(g_pp + rowQ) + lane, *reinterpret_cast<uint4*>(ppp));

        __half2 bsp[2];
        #pragma unroll
        for (int j2 = 0; j2 < 2; j2++)
            bsp[j2] = __floats2half2_rn(sv[2*j2], sv[2*j2+1]);
        #pragma unroll
        for (int j = 0; j < 4; j++) {
            segacc[j] += sv[j];
            if (sv[j] > 0.f) nnzacc += 1.f;
        }
        __stwt(reinterpret_cast<uint2*>(g_bs + pix * EE) + lane, *reinterpret_cast<uint2*>(bsp));
    }

    #pragma unroll
    for (int j = 0; j < 8; j++) {
        if (negacc[j] != 0.f) atomicAdd(&g_negsum[b*QQ + lane*8 + j], negacc[j]);
        if (psacc[j]  != 0.f) atomicAdd(&g_psum  [b*QQ + lane*8 + j], psacc[j]);
    }
    #pragma unroll
    for (int j = 0; j < 4; j++)
        if (segacc[j] != 0.f) atomicAdd(&g_segsum[b*EE + lane*4 + j], segacc[j]);
    #pragma unroll
    for (int o = 16; o; o >>= 1) nnzacc += __shfl_xor_sync(0xffffffffu, nnzacc, o);
    if (lane == 0 && nnzacc != 0.f) atomicAdd(&g_nnz[b], nnzacc);
}

// ---------------- MMA / cp.async helpers -------------------------------------
__device__ __forceinline__ void ldsm4t(unsigned& r0, unsigned& r1, unsigned& r2,
                                       unsigned& r3, const void* p) {
    unsigned a = (unsigned)__cvta_generic_to_shared(p);
    asm volatile("ldmatrix.sync.aligned.m8n8.x4.trans.shared.b16 {%0,%1,%2,%3},[%4];"
                 : "=r"(r0), "=r"(r1), "=r"(r2), "=r"(r3) : "r"(a));
}
__device__ __forceinline__ void mma16816(float* d, const unsigned* a, const unsigned* b) {
    asm volatile("mma.sync.aligned.m16n8k16.row.col.f32.f16.f16.f32 "
                 "{%0,%1,%2,%3},{%4,%5,%6,%7},{%8,%9},{%0,%1,%2,%3};"
                 : "+f"(d[0]), "+f"(d[1]), "+f"(d[2]), "+f"(d[3])
                 : "r"(a[0]), "r"(a[1]), "r"(a[2]), "r"(a[3]), "r"(b[0]), "r"(b[1]));
}
__device__ __forceinline__ void cpa16p(void* dst, const void* src, bool valid) {
    unsigned d = (unsigned)__cvta_generic_to_shared(dst);
    int sz = valid ? 16 : 0;
    asm volatile("cp.async.cg.shared.global [%0], [%1], 16, %2;"
                 :: "r"(d), "l"(src), "r"(sz) : "memory");
}
__device__ __forceinline__ void cpa_commit() {
    asm volatile("cp.async.commit_group;" ::: "memory");
}
template <int N> __device__ __forceinline__ void cpa_wait() {
    asm volatile("cp.async.wait_group %0;" :: "n"(N) : "memory");
}

// ---------------- stage 2: f16 GEMM, 16 warps, single-barrier pipeline -------
__global__ void __launch_bounds__(512) k_gemm() {
    __shared__ __align__(16) __half sA1[STG_][KT][SA];
    __shared__ __align__(16) __half sA2[STG_][KT][SA];
    __shared__ __align__(16) __half sBs[STG_][KT][SB];

    const int qh = blockIdx.x, b = blockIdx.y, pc = blockIdx.z;
    const int lane = threadIdx.x & 31, w = threadIdx.x >> 5;
    const int wq = w & 3, we = w >> 2;                 // 32q x 32e per warp
    const int p0 = pc * CHUNK;
    const int p1c = (p0 + CHUNK < PP) ? p0 + CHUNK : PP;
    const int nkt = (p1c - p0 + KT - 1) / KT;

    float acc1[2][4][4], acc2[2][4][4];
    #pragma unroll
    for (int i = 0; i < 2; i++)
        #pragma unroll
        for (int j = 0; j < 4; j++)
            #pragma unroll
            for (int k = 0; k < 4; k++) { acc1[i][j][k] = 0.f; acc2[i][j][k] = 0.f; }

    const int t = threadIdx.x;
    const int cr = (t & 255) >> 4, cc = t & 15;

    auto load_tile = [&](int kt, int bf) {
        const int p = p0 + kt * KT + cr;
        const bool v = p < p1c;
        const size_t pix = (size_t)b * PP + (v ? p : p0);
        if (t < 256) {
            cpa16p(&sA1[bf][cr][cc * 8], g_a1 + pix * QQ + qh * 128 + cc * 8, v);
            cpa16p(&sBs[bf][cr][cc * 8], g_bs + pix * EE + cc * 8, v);
        } else {
            cpa16p(&sA2[bf][cr][cc * 8], g_pp + pix * QQ + qh * 128 + cc * 8, v);
        }
    };

    #pragma unroll
    for (int s = 0; s < STG_ - 1; s++) {
        if (s < nkt) load_tile(s, s);
        cpa_commit();
    }

    const int g = lane >> 3, r = lane & 7;
    const __half2 z2 = __floats2half2_rn(0.f, 0.f);

    for (int kt = 0; kt < nkt; kt++) {
        const int bf = kt & (STG_ - 1);
        cpa_wait<STG_ - 2>();     // tile kt complete (<=2 groups pending)
        __syncthreads();          // tile kt visible + all warps done consuming kt-1

        // prefetch kt+3 into stage (kt-1)&3 (just released by the barrier)
        if (kt + STG_ - 1 < nkt) load_tile(kt + STG_ - 1, (kt + STG_ - 1) & (STG_ - 1));
        cpa_commit();

        unsigned bs[2][4], bt[2][4];
        const int brow = (g & 1) * 8 + r;
        #pragma unroll
        for (int h = 0; h < 2; h++) {
            const int bcol = we * 32 + h * 16 + (g >> 1) * 8;
            ldsm4t(bs[h][0], bs[h][1], bs[h][2], bs[h][3], &sBs[bf][brow][bcol]);
            #pragma unroll
            for (int k = 0; k < 4; k++) {
                __half2 vv = *reinterpret_cast<__half2*>(&bs[h][k]);
                __half2 tv = __hgt2(vv, z2);           // targ = (segval > 0)
                bt[h][k] = *reinterpret_cast<unsigned*>(&tv);
            }
        }
        #pragma unroll
        for (int mt = 0; mt < 2; mt++) {
            const int arow = (g >> 1) * 8 + r;
            const int acol = wq * 32 + mt * 16 + (g & 1) * 8;
            unsigned af1[4], af2[4];
            ldsm4t(af1[0], af1[1], af1[2], af1[3], &sA1[bf][arow][acol]);
            ldsm4t(af2[0], af2[1], af2[2], af2[3], &sA2[bf][arow][acol]);
            #pragma unroll
            for (int h = 0; h < 2; h++) {
                mma16816(acc1[mt][2*h],     af1, &bt[h][0]);
                mma16816(acc1[mt][2*h + 1], af1, &bt[h][2]);
                mma16816(acc2[mt][2*h],     af2, &bs[h][0]);
                mma16816(acc2[mt][2*h + 1], af2, &bs[h][2]);
            }
        }
    }

    // flush: global f32 RED (fire-and-forget, 9 partial adds per element)
    const size_t pbase = (size_t)b * (QQ * EE);
    #pragma unroll
    for (int mt = 0; mt < 2; mt++) {
        #pragma unroll
        for (int nt = 0; nt < 4; nt++) {
            const int q = qh * 128 + wq * 32 + mt * 16 + (lane >> 2);
            const int e = we * 32 + nt * 8 + (lane & 3) * 2;
            const size_t o1 = pbase + (size_t)q * EE + e;
            const size_t o2 = pbase + (size_t)(q + 8) * EE + e;
            atomicAdd(&g_M1[o1],     acc1[mt][nt][0]);
            atomicAdd(&g_M1[o1 + 1], acc1[mt][nt][1]);
            atomicAdd(&g_M1[o2],     acc1[mt][nt][2]);
            atomicAdd(&g_M1[o2 + 1], acc1[mt][nt][3]);
            atomicAdd(&g_M2[o1],     acc2[mt][nt][0]);
            atomicAdd(&g_M2[o1 + 1], acc2[mt][nt][1]);
            atomicAdd(&g_M2[o2],     acc2[mt][nt][2]);
            atomicAdd(&g_M2[o2 + 1], acc2[mt][nt][3]);
        }
    }
}

// ---------------- final: per-(b,q,e) costs + self-zero g_M -------------------
__global__ void __launch_bounds__(256) k_final(
    const float* __restrict__ logits, const float* __restrict__ ppos,
    const float* __restrict__ chol,   const float* __restrict__ tpos,
    const float* __restrict__ imsz,   float* __restrict__ out)
{
    const int idx = blockIdx.x * 256 + threadIdx.x;
    if (idx >= BB * QQ * EE) return;
    const int e = idx & (EE - 1);
    const int q = (idx >> 7) & (QQ - 1);
    const int b = idx >> 15;

    const float M1 = g_M1[idx];
    const float M2 = g_M2[idx];
    g_M1[idx] = 0.f;              // reset for next graph replay (thread owns idx)
    g_M2[idx] = 0.f;

    const float lgt = logits[b * QQ + q];
    const float cls = fmaxf(-lgt, 0.f) + log1pf(__expf(-fabsf(lgt)));
    const float nnz = fmaxf(g_nnz[b], 1.f);
    const float maskc = (M1 + g_negsum[b * QQ + q]) / nnz;
    const float dice  = 1.f - (2.f * M2 + 1.f) / (g_psum[b * QQ + q] + g_segsum[b * EE + e] + 1.f);

    const float px = ppos[(b * QQ + q) * 2 + 0], py = ppos[(b * QQ + q) * 2 + 1];
    const float tx = tpos[(b * EE + e) * 2 + 0], ty = tpos[(b * EE + e) * 2 + 1];
    const float d0 = px - tx, d1 = py - ty;
    const float a0 = fabsf(d0), a1 = fabsf(d1);
    const float h0 = (a0 < 1.f) ? 0.5f * d0 * d0 : a0 - 0.5f;
    const float h1 = (a1 < 1.f) ? 0.5f * d1 * d1 : a1 - 0.5f;
    const float hub = 0.5f * (h0 + h1);

    const float sx = imsz[b * 2 + 0], sy = imsz[b * 2 + 1];
    const float L00 = chol[(b * QQ + q) * 4 + 0];
    const float L10 = chol[(b * QQ + q) * 4 + 2];
    const float L11 = chol[(b * QQ + q) * 4 + 3];
    const float D0 = (tx - px) * sx, D1 = (ty - py) * sy;
    const float z0 = D0 / L00;
    const float z1 = (D1 - L10 * z0) / L11;
    const float nll = 0.5f * (z0 * z0 + z1 * z1) + 1.837877066409345f + logf(L00) + logf(L11);
    const float lik = 1.f - __expf(-nll);

    out[idx] = 2.f * cls + 5.f * maskc + 5.f * dice + hub + 0.5f * nll + 0.5f * lik;
}

// ---------------- launch -----------------------------------------------------
extern "C" void kernel_launch(void* const* d_in, const int* in_sizes, int n_in,
                              void* d_out, int out_size)
{
    const float* pred_logits = (const float*)d_in[0];
    const float* mlv         = (const float*)d_in[1];
    const void*  mm          = d_in[2];
    const float* seg         = (const float*)d_in[3];
    const float* ppos        = (const float*)d_in[4];
    const float* chol        = (const float*)d_in[5];
    const float* tpos        = (const float*)d_in[6];
    const float* imsz        = (const float*)d_in[7];
    float* out = (float*)d_out;

    int nvec = in_sizes[2] / 16;
    if (nvec > 4096) nvec = 4096;

    k_pre<<<2, 1024>>>((const uint4*)mm, nvec);

    dim3 g1(128, BB);
    k_stage1<<<g1, 128>>>(mlv, mm, seg);

    dim3 g2(2, BB, NPC);
    k_gemm<<<g2, 512>>>();

    k_final<<<(BB * QQ * EE + 255) / 256, 256>>>(pred_logits, ppos, chol, tpos, imsz, out);
}